// round 7
// baseline (speedup 1.0000x reference)
#include <cuda_runtime.h>
#include <stdint.h>

#define HH 1024
#define WW 2048
#define HW (HH * WW)              // 2,097,152 pixels
#define NI 128                    // instances
#define NB 10                     // "thing" classes 24..33
#define NBINS (NI * NB)           // 1280
#define THREADS 256
#define NGRP (HW / 4)             // 524,288 four-pixel groups
#define NBLK_STATS (NGRP / THREADS)      // 2048 stats blocks

#define SEC_PER_CH (HW / 8)              // 262,144 sectors (32B) per channel
#define NSEC ((size_t)NI * SEC_PER_CH)   // 33,554,432 sectors total
#define NFLAGW ((int)(NSEC / 16))        // 2,097,152 uint32 flag words (8MB)

// mask kernel: thread owns 128B = 4 sectors = 32 px of one channel
#define CHUNKS_PER_CH (HW / 32)          // 65,536 chunks per channel
#define CH_SHIFT 16                      // log2(CHUNKS_PER_CH)
#define CH_MASK (CHUNKS_PER_CH - 1)
#define NTHR_MASK ((size_t)NI * CHUNKS_PER_CH)     // 8,388,608 threads
#define NBLK_MASK ((int)(NTHR_MASK / THREADS))     // 32,768 blocks

// Scratch (no cudaMalloc). Zero-initialized at load. g_flags: K1 sets bits,
// K2 clears exactly the dirty bytes (each byte is exclusive to one K2
// thread) -> clean state for every graph replay. Bins reset by finalize.
__device__ uint8_t      g_inst8[HW];     // per-pixel instance id (0 = stuff)
__device__ unsigned int g_flags[NFLAGW]; // 1 bit per 32B output sector
__device__ int          g_counts[NBINS];
__device__ float        g_sums[NBINS];

// ---------------------------------------------------------------------------
// Kernel 1: stats prepass + sector-flag build (no ticket, no fence).
//   - inst = (24 <= seg <= 33) ? instance_maps : 0  -> g_inst8 (uchar4)
//   - shared-mem histograms -> RED flush to global bins
//   - for each nonzero-instance pixel: atomicOr the flag bit of output
//     sector (inst-1)*SEC_PER_CH + (p>>3)   (~612K scattered REDGs)
//   Flag word layout: word w, byte (sec>>2)&3, bit sec&3  -> K2 can test a
//   whole 4-sector chunk with ONE byte load.
// ---------------------------------------------------------------------------
__global__ void __launch_bounds__(THREADS)
stats_kernel(const int4*   __restrict__ seg4,
             const int4*   __restrict__ inst4,
             const float4* __restrict__ probs4) {
    __shared__ int   s_cnt[NBINS];
    __shared__ float s_sum[NBINS];

    const int tid = threadIdx.x;
    for (int i = tid; i < NBINS; i += THREADS) { s_cnt[i] = 0; s_sum[i] = 0.0f; }
    __syncthreads();

    const int t  = blockIdx.x * THREADS + tid;      // 4-pixel group index
    const int p0 = t * 4;
    const int psec = p0 >> 3;                       // all 4 px share one sector

    const int4 sg = seg4[t];
    const int4 im = inst4[t];
    const int ss[4] = { sg.x, sg.y, sg.z, sg.w };
    const int iv[4] = { im.x, im.y, im.z, im.w };
    int ii[4];

    int prev_id = -1;
    #pragma unroll
    for (int j = 0; j < 4; ++j) {
        const int s = ss[j];
        const int inst = (s >= 24 && s <= 33) ? iv[j] : 0;
        ii[j] = inst;
        if (inst > 0) {
            atomicAdd(&s_cnt[(inst - 1) * NB + (s - 24)], 1);
            if (inst != prev_id) {                   // cheap dedupe
                const unsigned int sec = (unsigned)(inst - 1) * SEC_PER_CH + psec;
                const unsigned int bit = 8u * ((sec >> 2) & 3u) + (sec & 3u);
                atomicOr(&g_flags[sec >> 4], 1u << bit);
                prev_id = inst;
            }
        }
    }

    uchar4 packed;
    packed.x = (uint8_t)ii[0];
    packed.y = (uint8_t)ii[1];
    packed.z = (uint8_t)ii[2];
    packed.w = (uint8_t)ii[3];
    ((uchar4*)g_inst8)[t] = packed;

    if (ii[0] | ii[1] | ii[2] | ii[3]) {
        #pragma unroll
        for (int c = 0; c < NB; ++c) {
            const float4 pv = __ldg(&probs4[(size_t)(24 + c) * NGRP + t]);
            const float pa[4] = { pv.x, pv.y, pv.z, pv.w };
            #pragma unroll
            for (int j = 0; j < 4; ++j)
                if (ii[j] > 0)
                    atomicAdd(&s_sum[(ii[j] - 1) * NB + c], pa[j]);
        }
    }

    __syncthreads();
    for (int i = tid; i < NBINS; i += THREADS) {
        const int   cv = s_cnt[i];
        const float sv = s_sum[i];
        if (cv)          atomicAdd(&g_counts[i], cv);
        if (sv != 0.0f)  atomicAdd(&g_sums[i], sv);
    }
}

// one-hot float4 from 4 packed ids vs channel id
__device__ __forceinline__ float4 onehot4(unsigned int v, int id) {
    float4 f;
    f.x = ((int)( v        & 0xFF) == id) ? 1.0f : 0.0f;
    f.y = ((int)((v >>  8) & 0xFF) == id) ? 1.0f : 0.0f;
    f.z = ((int)((v >> 16) & 0xFF) == id) ? 1.0f : 0.0f;
    f.w = ((int)( v >> 24        ) == id) ? 1.0f : 0.0f;
    return f;
}

// ---------------------------------------------------------------------------
// Kernel 2: flag-guided fill + finalize.
//   block 0: finalize tail outputs from completed bins, reset bins (R6-proven).
//   other blocks: thread t owns 128B (32 px) of channel t>>16.
//     flag byte == 0 (93% of threads): 8 pure streaming zero stores — the
//       proven 6.5 TB/s path, +1 byte load.
//     flag byte != 0: load 32 ids (2x uint4), compute 8 one-hot float4s,
//       store them, clear own flag byte (self-clean for next replay).
// ---------------------------------------------------------------------------
__global__ void __launch_bounds__(THREADS)
mask_kernel(const float* __restrict__ inst_probs,
            float*       __restrict__ out) {
    const int tid = threadIdx.x;
    const int b   = blockIdx.x;

    if (b == 0) {
        if (tid < NI) {
            const int i = tid;
            int tot = 0, best = 0, bestc = 0;
            #pragma unroll
            for (int c = 0; c < NB; ++c) {
                const int v = g_counts[i * NB + c];
                tot += v;
                if (v > best) { best = v; bestc = c; }   // first-occurrence ties
            }
            float cls = 0.0f, segp = 0.0f;
            if (tot > 0) {
                cls  = (float)(24 + bestc);
                segp = g_sums[i * NB + bestc] / (float)tot;
            }
            float* tail = out + (size_t)NI * HW;
            tail[0 * NI + i] = cls;                      // inst_class
            tail[1 * NI + i] = inst_probs[i];            // instance_probs
            tail[2 * NI + i] = segp;                     // seg_prob
            tail[3 * NI + i] = (float)tot;               // total
            tail[4 * NI + i] = (tot > 0) ? 1.0f : 0.0f;  // valid
        }
        __syncthreads();
        for (int i = tid; i < NBINS; i += THREADS) {     // reset for replay
            g_counts[i] = 0;
            g_sums[i]   = 0.0f;
        }
        return;
    }

    const size_t t    = (size_t)(b - 1) * THREADS + tid; // 128B-chunk index
    const int    chan = (int)(t >> CH_SHIFT);            // 0..127
    const int    g    = (int)(t & CH_MASK);              // chunk within channel
    const int    id   = chan + 1;

    const unsigned char fb = ((const unsigned char*)g_flags)[t];

    float4* dst = (float4*)(out + (size_t)chan * HW) + (size_t)g * 8;

    if (fb == 0) {
        const float4 z = make_float4(0.f, 0.f, 0.f, 0.f);
        #pragma unroll
        for (int k = 0; k < 8; ++k)
            __stcs(&dst[k], z);
        return;
    }

    // rare path (~7% of threads): compute the 32 one-hot values
    const uint4 w0 = ((const uint4*)g_inst8)[g * 2];
    const uint4 w1 = ((const uint4*)g_inst8)[g * 2 + 1];
    __stcs(&dst[0], onehot4(w0.x, id));
    __stcs(&dst[1], onehot4(w0.y, id));
    __stcs(&dst[2], onehot4(w0.z, id));
    __stcs(&dst[3], onehot4(w0.w, id));
    __stcs(&dst[4], onehot4(w1.x, id));
    __stcs(&dst[5], onehot4(w1.y, id));
    __stcs(&dst[6], onehot4(w1.z, id));
    __stcs(&dst[7], onehot4(w1.w, id));

    ((unsigned char*)g_flags)[t] = 0;    // self-clean (byte exclusive to t)
}

// ---------------------------------------------------------------------------
extern "C" void kernel_launch(void* const* d_in, const int* in_sizes, int n_in,
                              void* d_out, int out_size) {
    const int*   seg    = (const int*)  d_in[0];   // (H, W) int32
    const int*   inst   = (const int*)  d_in[1];   // (H, W) int32
    const float* probs  = (const float*)d_in[2];   // (C, H, W) float32
    const float* iprobs = (const float*)d_in[3];   // (128,) float32
    float* out = (float*)d_out;

    stats_kernel<<<NBLK_STATS, THREADS>>>(
        (const int4*)seg, (const int4*)inst, (const float4*)probs);
    mask_kernel<<<NBLK_MASK + 1, THREADS>>>(iprobs, out);
}

// round 8
// speedup vs baseline: 1.7520x; 1.7520x over previous
#include <cuda_runtime.h>
#include <stdint.h>

#define HH 1024
#define WW 2048
#define HW (HH * WW)              // 2,097,152 pixels
#define NI 128                    // instances
#define NB 10                     // "thing" classes 24..33
#define NBINS (NI * NB)           // 1280
#define THREADS 256
#define NGRP (HW / 4)             // 524,288 float4 groups per channel

// stats geometry: 8 px per thread == one 32B output sector per thread
#define NSECT (HW / 8)                       // 262,144 sectors
#define NBLK_STATS (NSECT / THREADS)         // 1024 stats blocks

// fill geometry
#define NQ ((size_t)NI * HW / 4)             // float4 count of mask region
#define NBLK_FILL ((int)(NQ / THREADS))      // 262,144 fill blocks
#define NBLK_A (NBLK_STATS + NBLK_FILL)

// worklist: worst case 8 entries per stats thread (exact bound)
#define NENT (NSECT * 8)                     // 2,097,152 entries (16MB)
#define NBLK_SCAT (NENT / THREADS)           // 8,192 scatter blocks

// Scratch (no cudaMalloc). Zero-initialized at load. g_entries slots are
// self-cleaned by kernel B (each thread clears exactly the slot it consumed);
// bins + g_ecount reset by B's finalize block. Deterministic across replays.
__device__ unsigned long long g_entries[NENT];
__device__ unsigned int       g_ecount;
__device__ int                g_counts[NBINS];
__device__ float              g_sums[NBINS];

// ---------------------------------------------------------------------------
// Kernel A: fused zero-fill + stats + worklist build.
//   blocks [0, NBLK_STATS): stats path, 8 px (= 1 output sector) per thread:
//     - ids[j] = (24 <= seg <= 33) ? instance_maps : 0
//     - shared-mem histograms -> RED flush to global bins
//     - prob sums over the 10 thing channels (only if any thing pixel)
//     - per distinct id in the 8 px: emit entry (sector<<16 | id<<8 | mask)
//       via block-aggregated append (one global atomicAdd per block).
//   blocks [NBLK_STATS, NBLK_A): pure float4 streaming zero-fill — the
//     dependency-free 6.5 TB/s path, untouched.
// ---------------------------------------------------------------------------
__global__ void __launch_bounds__(THREADS)
fill_stats_kernel(const int4*   __restrict__ seg4,
                  const int4*   __restrict__ inst4,
                  const float4* __restrict__ probs4,
                  float4*       __restrict__ out4) {
    const int tid = threadIdx.x;
    const int b   = blockIdx.x;

    if (b >= NBLK_STATS) {
        // ---------------- zero-fill path (pure streaming stores) ----------
        const size_t i = (size_t)(b - NBLK_STATS) * THREADS + tid;
        __stcs(&out4[i], make_float4(0.f, 0.f, 0.f, 0.f));
        return;
    }

    // -------------------- stats + worklist path -------------------------
    __shared__ int                s_cnt[NBINS];
    __shared__ float              s_sum[NBINS];
    __shared__ unsigned long long s_ent[THREADS * 8];
    __shared__ unsigned int       s_n, s_base;

    for (int i = tid; i < NBINS; i += THREADS) { s_cnt[i] = 0; s_sum[i] = 0.0f; }
    if (tid == 0) s_n = 0u;
    __syncthreads();

    const int t = b * THREADS + tid;            // sector index (8 px)

    const int4 sgA = seg4[2 * t];
    const int4 sgB = seg4[2 * t + 1];
    const int4 imA = inst4[2 * t];
    const int4 imB = inst4[2 * t + 1];
    const int ss[8] = { sgA.x, sgA.y, sgA.z, sgA.w, sgB.x, sgB.y, sgB.z, sgB.w };
    const int iv[8] = { imA.x, imA.y, imA.z, imA.w, imB.x, imB.y, imB.z, imB.w };
    int ids[8];
    int any = 0;

    #pragma unroll
    for (int j = 0; j < 8; ++j) {
        const int s  = ss[j];
        const int id = (s >= 24 && s <= 33) ? iv[j] : 0;
        ids[j] = id;
        any |= id;
        if (id > 0)
            atomicAdd(&s_cnt[(id - 1) * NB + (s - 24)], 1);
    }

    if (any) {
        // prob sums
        #pragma unroll
        for (int c = 0; c < NB; ++c) {
            const size_t base = (size_t)(24 + c) * NGRP + 2 * t;
            const float4 pvA = __ldg(&probs4[base]);
            const float4 pvB = __ldg(&probs4[base + 1]);
            const float pa[8] = { pvA.x, pvA.y, pvA.z, pvA.w,
                                  pvB.x, pvB.y, pvB.z, pvB.w };
            #pragma unroll
            for (int j = 0; j < 8; ++j)
                if (ids[j] > 0)
                    atomicAdd(&s_sum[(ids[j] - 1) * NB + c], pa[j]);
        }

        // worklist entries: one per distinct id in this sector
        unsigned long long loc[8];
        int ln = 0;
        #pragma unroll
        for (int j = 0; j < 8; ++j) {
            const int id = ids[j];
            if (id == 0) continue;
            bool first = true;
            #pragma unroll
            for (int k = 0; k < 8; ++k)
                if (k < j && ids[k] == id) first = false;
            if (first) {
                unsigned int mask = 0;
                #pragma unroll
                for (int k = 0; k < 8; ++k)
                    if (k >= j && ids[k] == id) mask |= 1u << k;
                loc[ln++] = ((unsigned long long)t << 16)
                          | ((unsigned long long)id << 8)
                          | (unsigned long long)mask;
            }
        }
        if (ln) {
            const unsigned int ofs = atomicAdd(&s_n, (unsigned)ln);
            for (int e = 0; e < ln; ++e)
                s_ent[ofs + e] = loc[e];
        }
    }

    __syncthreads();
    if (tid == 0)
        s_base = atomicAdd(&g_ecount, s_n);
    __syncthreads();

    const unsigned int n    = s_n;
    const unsigned int base = s_base;
    for (unsigned int i = tid; i < n; i += THREADS)
        g_entries[base + i] = s_ent[i];

    // flush bins
    for (int i = tid; i < NBINS; i += THREADS) {
        const int   cv = s_cnt[i];
        const float sv = s_sum[i];
        if (cv)          atomicAdd(&g_counts[i], cv);
        if (sv != 0.0f)  atomicAdd(&g_sums[i], sv);
    }
}

// ---------------------------------------------------------------------------
// Kernel B: worklist-driven full-sector scatter + finalize.
//   block 0: finalize the 5 tail outputs from the completed bins, reset the
//            bins and g_ecount for the next replay (B never reads g_ecount,
//            so the reset cannot race the scatter blocks).
//   blocks [1, NBLK_SCAT]: coalesced scan of g_entries; each nonzero entry
//     writes its full 32B output sector (2x float4, no RMW) and self-clears
//     its slot so the next replay sees a clean array.
// ---------------------------------------------------------------------------
__global__ void __launch_bounds__(THREADS)
scatter_kernel(const float* __restrict__ inst_probs,
               float*       __restrict__ out) {
    const int tid = threadIdx.x;
    const int b   = blockIdx.x;

    if (b == 0) {
        if (tid < NI) {
            const int i = tid;
            int tot = 0, best = 0, bestc = 0;
            #pragma unroll
            for (int c = 0; c < NB; ++c) {
                const int v = g_counts[i * NB + c];
                tot += v;
                if (v > best) { best = v; bestc = c; }   // first-occurrence ties
            }
            float cls = 0.0f, segp = 0.0f;
            if (tot > 0) {
                cls  = (float)(24 + bestc);
                segp = g_sums[i * NB + bestc] / (float)tot;
            }
            float* tail = out + (size_t)NI * HW;
            tail[0 * NI + i] = cls;                      // inst_class
            tail[1 * NI + i] = inst_probs[i];            // instance_probs
            tail[2 * NI + i] = segp;                     // seg_prob
            tail[3 * NI + i] = (float)tot;               // total
            tail[4 * NI + i] = (tot > 0) ? 1.0f : 0.0f;  // valid
        }
        __syncthreads();
        for (int i = tid; i < NBINS; i += THREADS) {     // reset for replay
            g_counts[i] = 0;
            g_sums[i]   = 0.0f;
        }
        if (tid == 0) g_ecount = 0u;
        return;
    }

    const size_t i = (size_t)(b - 1) * THREADS + tid;
    const unsigned long long e = g_entries[i];
    if (e == 0ull) return;

    const unsigned int sec  = (unsigned int)(e >> 16);         // 0..262143
    const int          id   = (int)((e >> 8) & 0xFFull);       // 1..128
    const unsigned int mask = (unsigned int)(e & 0xFFull);

    float4 lo, hi;
    lo.x = (mask & 0x01u) ? 1.0f : 0.0f;
    lo.y = (mask & 0x02u) ? 1.0f : 0.0f;
    lo.z = (mask & 0x04u) ? 1.0f : 0.0f;
    lo.w = (mask & 0x08u) ? 1.0f : 0.0f;
    hi.x = (mask & 0x10u) ? 1.0f : 0.0f;
    hi.y = (mask & 0x20u) ? 1.0f : 0.0f;
    hi.z = (mask & 0x40u) ? 1.0f : 0.0f;
    hi.w = (mask & 0x80u) ? 1.0f : 0.0f;

    float4* dst = (float4*)(out + (size_t)(id - 1) * HW + (size_t)sec * 8);
    __stcs(&dst[0], lo);
    __stcs(&dst[1], hi);

    g_entries[i] = 0ull;                 // self-clean for next replay
}

// ---------------------------------------------------------------------------
extern "C" void kernel_launch(void* const* d_in, const int* in_sizes, int n_in,
                              void* d_out, int out_size) {
    const int*   seg    = (const int*)  d_in[0];   // (H, W) int32
    const int*   inst   = (const int*)  d_in[1];   // (H, W) int32
    const float* probs  = (const float*)d_in[2];   // (C, H, W) float32
    const float* iprobs = (const float*)d_in[3];   // (128,) float32
    float* out = (float*)d_out;

    fill_stats_kernel<<<NBLK_A, THREADS>>>(
        (const int4*)seg, (const int4*)inst, (const float4*)probs,
        (float4*)out);
    scatter_kernel<<<NBLK_SCAT + 1, THREADS>>>(iprobs, out);
}

// round 9
// speedup vs baseline: 1.8511x; 1.0565x over previous
#include <cuda_runtime.h>
#include <stdint.h>

#define HH 1024
#define WW 2048
#define HW (HH * WW)              // 2,097,152 pixels
#define NI 128                    // instances
#define NB 10                     // "thing" classes 24..33
#define NBINS (NI * NB)           // 1280
#define THREADS 256
#define NGRP (HW / 4)             // 524,288 float4 groups per channel

// stats geometry: 8 px per thread == one 32B output sector per thread
#define NSECT (HW / 8)                       // 262,144 sectors
#define NBLK_STATS (NSECT / THREADS)         // 1024 stats blocks

// fill geometry
#define NQ ((size_t)NI * HW / 4)             // float4 count of mask region
#define NBLK_FILL ((int)(NQ / THREADS))      // 262,144 fill blocks
#define NBLK_A (NBLK_STATS + NBLK_FILL)

// worklist: exact worst case 8 entries per sector
#define NENT (NSECT * 8)                     // 2,097,152 entries (16MB)
#define NBLK_SCAT (NENT / THREADS)           // 8,192 scatter blocks

// Scratch (no cudaMalloc). Zero-initialized at load.
// Reset protocol per run: bins reset by B; entries self-cleaned by C;
// g_isum + g_ecount reset by D. g_cls/g_total fully rewritten by B.
__device__ unsigned long long g_entries[NENT];
__device__ unsigned int       g_ecount;
__device__ int                g_counts[NBINS];
__device__ int                g_cls[NI];      // argmax class (24..33) or 0
__device__ int                g_total[NI];
__device__ float              g_isum[NI];

// ---------------------------------------------------------------------------
// Kernel A: fused zero-fill + counts + worklist build. NO probability reads.
//   blocks [0, NBLK_STATS): 8 px (= 1 output sector) per thread:
//     - ids[j] = (24 <= seg <= 33) ? instance_maps : 0
//     - shared-mem count histogram -> RED flush
//     - per distinct id in the sector: entry (sector<<16 | id<<8 | mask)
//       via block-aggregated append.
//   blocks [NBLK_STATS, NBLK_A): pure float4 streaming zero-fill.
// ---------------------------------------------------------------------------
__global__ void __launch_bounds__(THREADS)
fill_stats_kernel(const int4* __restrict__ seg4,
                  const int4* __restrict__ inst4,
                  float4*     __restrict__ out4) {
    const int tid = threadIdx.x;
    const int b   = blockIdx.x;

    if (b >= NBLK_STATS) {
        const size_t i = (size_t)(b - NBLK_STATS) * THREADS + tid;
        __stcs(&out4[i], make_float4(0.f, 0.f, 0.f, 0.f));
        return;
    }

    __shared__ int                s_cnt[NBINS];
    __shared__ unsigned long long s_ent[THREADS * 8];
    __shared__ unsigned int       s_n, s_base;

    for (int i = tid; i < NBINS; i += THREADS) s_cnt[i] = 0;
    if (tid == 0) s_n = 0u;
    __syncthreads();

    const int t = b * THREADS + tid;            // sector index (8 px)

    const int4 sgA = seg4[2 * t];
    const int4 sgB = seg4[2 * t + 1];
    const int4 imA = inst4[2 * t];
    const int4 imB = inst4[2 * t + 1];
    const int ss[8] = { sgA.x, sgA.y, sgA.z, sgA.w, sgB.x, sgB.y, sgB.z, sgB.w };
    const int iv[8] = { imA.x, imA.y, imA.z, imA.w, imB.x, imB.y, imB.z, imB.w };
    int ids[8];
    int any = 0;

    #pragma unroll
    for (int j = 0; j < 8; ++j) {
        const int s  = ss[j];
        const int id = (s >= 24 && s <= 33) ? iv[j] : 0;
        ids[j] = id;
        any |= id;
        if (id > 0)
            atomicAdd(&s_cnt[(id - 1) * NB + (s - 24)], 1);
    }

    if (any) {
        unsigned long long loc[8];
        int ln = 0;
        #pragma unroll
        for (int j = 0; j < 8; ++j) {
            const int id = ids[j];
            if (id == 0) continue;
            bool first = true;
            #pragma unroll
            for (int k = 0; k < 8; ++k)
                if (k < j && ids[k] == id) first = false;
            if (first) {
                unsigned int mask = 0;
                #pragma unroll
                for (int k = 0; k < 8; ++k)
                    if (k >= j && ids[k] == id) mask |= 1u << k;
                loc[ln++] = ((unsigned long long)t << 16)
                          | ((unsigned long long)id << 8)
                          | (unsigned long long)mask;
            }
        }
        if (ln) {
            const unsigned int ofs = atomicAdd(&s_n, (unsigned)ln);
            for (int e = 0; e < ln; ++e)
                s_ent[ofs + e] = loc[e];
        }
    }

    __syncthreads();
    if (tid == 0)
        s_base = atomicAdd(&g_ecount, s_n);
    __syncthreads();

    const unsigned int n    = s_n;
    const unsigned int base = s_base;
    for (unsigned int i = tid; i < n; i += THREADS)
        g_entries[base + i] = s_ent[i];

    for (int i = tid; i < NBINS; i += THREADS) {
        const int cv = s_cnt[i];
        if (cv) atomicAdd(&g_counts[i], cv);
    }
}

// ---------------------------------------------------------------------------
// Kernel B (1 block, 128 threads): per-instance argmax + 4 tail outputs.
//   Also publishes g_cls / g_total for kernels C/D and resets the bins.
// ---------------------------------------------------------------------------
__global__ void __launch_bounds__(NI)
argmax_kernel(const float* __restrict__ inst_probs,
              float*       __restrict__ out) {
    const int i = threadIdx.x;                  // 0..127
    int tot = 0, best = 0, bestc = 0;
    #pragma unroll
    for (int c = 0; c < NB; ++c) {
        const int v = g_counts[i * NB + c];
        tot += v;
        if (v > best) { best = v; bestc = c; }  // first-occurrence ties
    }
    const int cls = (tot > 0) ? (24 + bestc) : 0;
    g_cls[i]   = cls;
    g_total[i] = tot;

    float* tail = out + (size_t)NI * HW;
    tail[0 * NI + i] = (float)cls;              // inst_class
    tail[1 * NI + i] = inst_probs[i];           // instance_probs
    tail[3 * NI + i] = (float)tot;              // total
    tail[4 * NI + i] = (tot > 0) ? 1.0f : 0.0f; // valid

    __syncthreads();
    // reset bins for next replay (each thread read its own 10 before this)
    for (int k = i; k < NBINS; k += NI) g_counts[k] = 0;
}

// ---------------------------------------------------------------------------
// Kernel C: single worklist scan -> scatter one-hot sectors + gather the
//   argmax-channel prob sector per entry. Entries are compacted [0,count),
//   so blocks beyond the count exit immediately (g_ecount is reset in D,
//   strictly after C). Each entry:
//     - writes its full 32B output sector (unique (sector,channel) pair,
//       zeros included -> no RMW, no conflicts)
//     - loads probs[g_cls[id]][sector] (32B) and accumulates the masked
//       pixel values into shared per-instance sums -> RED to g_isum
//     - self-cleans its slot.
// ---------------------------------------------------------------------------
__global__ void __launch_bounds__(THREADS)
scatter_gather_kernel(const float4* __restrict__ probs4,
                      float*        __restrict__ out) {
    const unsigned int count = g_ecount;
    if ((unsigned int)blockIdx.x * THREADS >= count) return;   // block-uniform

    __shared__ float s_isum[NI];
    const int tid = threadIdx.x;
    if (tid < NI) s_isum[tid] = 0.0f;
    __syncthreads();

    const size_t i = (size_t)blockIdx.x * THREADS + tid;
    if (i < count) {
        const unsigned long long e = g_entries[i];
        const unsigned int sec  = (unsigned int)(e >> 16);      // 0..262143
        const int          id   = (int)((e >> 8) & 0xFFull);    // 1..128
        const unsigned int mask = (unsigned int)(e & 0xFFull);

        // ---- scatter: full 32B one-hot sector ----
        float4 lo, hi;
        lo.x = (mask & 0x01u) ? 1.0f : 0.0f;
        lo.y = (mask & 0x02u) ? 1.0f : 0.0f;
        lo.z = (mask & 0x04u) ? 1.0f : 0.0f;
        lo.w = (mask & 0x08u) ? 1.0f : 0.0f;
        hi.x = (mask & 0x10u) ? 1.0f : 0.0f;
        hi.y = (mask & 0x20u) ? 1.0f : 0.0f;
        hi.z = (mask & 0x40u) ? 1.0f : 0.0f;
        hi.w = (mask & 0x80u) ? 1.0f : 0.0f;
        float4* dst = (float4*)(out + (size_t)(id - 1) * HW + (size_t)sec * 8);
        __stcs(&dst[0], lo);
        __stcs(&dst[1], hi);

        // ---- gather: argmax-channel prob sector for this entry ----
        const int c = g_cls[id - 1];            // 24..33 (tot>0 guaranteed)
        const float4* p = &probs4[(size_t)c * NGRP + (size_t)sec * 2];
        const float4 pa = __ldg(&p[0]);
        const float4 pb = __ldg(&p[1]);
        float s = 0.0f;
        if (mask & 0x01u) s += pa.x;
        if (mask & 0x02u) s += pa.y;
        if (mask & 0x04u) s += pa.z;
        if (mask & 0x08u) s += pa.w;
        if (mask & 0x10u) s += pb.x;
        if (mask & 0x20u) s += pb.y;
        if (mask & 0x40u) s += pb.z;
        if (mask & 0x80u) s += pb.w;
        atomicAdd(&s_isum[id - 1], s);

        g_entries[i] = 0ull;                    // self-clean for next replay
    }

    __syncthreads();
    if (tid < NI) {
        const float v = s_isum[tid];
        if (v != 0.0f) atomicAdd(&g_isum[tid], v);
    }
}

// ---------------------------------------------------------------------------
// Kernel D (1 block, 128 threads): seg_prob = isum/total; reset g_isum and
//   g_ecount for the next graph replay.
// ---------------------------------------------------------------------------
__global__ void __launch_bounds__(NI)
segprob_kernel(float* __restrict__ out) {
    const int i = threadIdx.x;
    const int tot = g_total[i];
    float* tail = out + (size_t)NI * HW;
    tail[2 * NI + i] = (tot > 0) ? (g_isum[i] / (float)tot) : 0.0f;
    g_isum[i] = 0.0f;
    if (i == 0) g_ecount = 0u;
}

// ---------------------------------------------------------------------------
extern "C" void kernel_launch(void* const* d_in, const int* in_sizes, int n_in,
                              void* d_out, int out_size) {
    const int*   seg    = (const int*)  d_in[0];   // (H, W) int32
    const int*   inst   = (const int*)  d_in[1];   // (H, W) int32
    const float* probs  = (const float*)d_in[2];   // (C, H, W) float32
    const float* iprobs = (const float*)d_in[3];   // (128,) float32
    float* out = (float*)d_out;

    fill_stats_kernel<<<NBLK_A, THREADS>>>(
        (const int4*)seg, (const int4*)inst, (float4*)out);
    argmax_kernel<<<1, NI>>>(iprobs, out);
    scatter_gather_kernel<<<NBLK_SCAT, THREADS>>>((const float4*)probs, out);
    segprob_kernel<<<1, NI>>>(out);
}